// round 15
// baseline (speedup 1.0000x reference)
#include <cuda_runtime.h>
#include <cstdint>

// Voxelization: per-point voxel coords.  FINAL — converged at the mixed-R/W
// HBM ceiling (29.0-29.2us kernel, DRAM 74-75%, ~5.9 TB/s sustained).
//
//   input : points [N, 4] float32 (x, y, z, feat)
//   output: [3, N] float32, rows = (z, y, x); -1.0f for out-of-range points.
//
// Constants (must match the fp32 reference exactly):
//   voxel_size = (0.05, 0.05, 0.1)
//   pc_range mins = (0.0, -40.0, -3.0)
//   grid = (1408, 1600, 40)
//
// Search summary (all measured on GB300):
//   PPT=4, u32 idx, default cache, 256 thr  -> 29.0us kernel  [WINNER]
//   PPT=8 front-batch                        -> -11% (L1tex queue overflow)
//   __stcs stores                            -> -6%
//   __ldcs loads                             -> -3%
//   512-thread blocks                        -> neutral
// Numerics: __fdiv_rn + floorf matches the JAX fp32 reference bit-for-bit
// (0.05f not exactly representable; reciprocal-mul flips boundary voxels).

#define VSX 0.05f
#define VSY 0.05f
#define VSZ 0.1f
#define MINX 0.0f
#define MINY -40.0f
#define MINZ -3.0f
#define GXF 1408.0f
#define GYF 1600.0f
#define GZF 40.0f

__device__ __forceinline__ void voxel_coord(const float4 p, float& cx, float& cy, float& cz) {
    const float fx = floorf(__fdiv_rn(p.x - MINX, VSX));
    const float fy = floorf(__fdiv_rn(p.y - MINY, VSY));
    const float fz = floorf(__fdiv_rn(p.z - MINZ, VSZ));
    const bool valid = (fx >= 0.0f) & (fx < GXF) &
                       (fy >= 0.0f) & (fy < GYF) &
                       (fz >= 0.0f) & (fz < GZF);
    cx = valid ? fx : -1.0f;
    cy = valid ? fy : -1.0f;
    cz = valid ? fz : -1.0f;
}

__global__ __launch_bounds__(256)
void voxelize_kernel(const float4* __restrict__ pts,
                     float* __restrict__ out,   // [3, N]: z row, y row, x row
                     unsigned int n) {
    const unsigned int g = blockIdx.x * blockDim.x + threadIdx.x;
    const unsigned int base = g << 2;   // 4 points per thread; 3*n < 2^31 fits u32
    if (base >= n) return;

    float* __restrict__ out_z = out;
    float* __restrict__ out_y = out + n;
    float* __restrict__ out_x = out + 2u * n;

    if (base + 3u < n) {
        // Vector path: 4 x LDG.128 in, 3 x STG.128 out (default cache policy).
        const float4 p0 = pts[base + 0u];
        const float4 p1 = pts[base + 1u];
        const float4 p2 = pts[base + 2u];
        const float4 p3 = pts[base + 3u];

        float4 vz, vy, vx;
        voxel_coord(p0, vx.x, vy.x, vz.x);
        voxel_coord(p1, vx.y, vy.y, vz.y);
        voxel_coord(p2, vx.z, vy.z, vz.z);
        voxel_coord(p3, vx.w, vy.w, vz.w);

        *reinterpret_cast<float4*>(out_z + base) = vz;
        *reinterpret_cast<float4*>(out_y + base) = vy;
        *reinterpret_cast<float4*>(out_x + base) = vx;
    } else {
        // Scalar tail (only hit if n % 4 != 0).
        for (unsigned int i = base; i < n; ++i) {
            const float4 p = pts[i];
            float cx, cy, cz;
            voxel_coord(p, cx, cy, cz);
            out_z[i] = cz;
            out_y[i] = cy;
            out_x[i] = cx;
        }
    }
}

extern "C" void kernel_launch(void* const* d_in, const int* in_sizes, int n_in,
                              void* d_out, int out_size) {
    const float4* pts = (const float4*)d_in[0];
    float* out = (float*)d_out;
    const unsigned int n = (unsigned int)(in_sizes[0] / 4);   // points are [N, 4] floats

    const unsigned int n_groups = (n + 3u) / 4u;   // 4 points per thread
    const unsigned int threads = 256u;
    const unsigned int blocks = (n_groups + threads - 1u) / threads;
    voxelize_kernel<<<blocks, threads>>>(pts, out, n);
}